// round 8
// baseline (speedup 1.0000x reference)
#include <cuda_runtime.h>
#include <cuda_bf16.h>
#include <cstdint>

#define B_ 8
#define N_ 2048
#define D_ 128

// ---------------- scratch (__device__ globals: allocation-free) ----------------
__device__ __align__(16) unsigned int g_embT[(size_t)B_ * D_ * N_ / 2];    // bf16 [b][d][i]
__device__ __align__(16) float g_snT[(size_t)B_ * D_ * N_];                // fp32 [b][d][j]
__device__ int g_degcnt[B_ * N_];                                          // nonzero counts

// ---------------- helpers ----------------
__device__ __forceinline__ uint32_t smem_to_u32(const void* p) {
    uint32_t a;
    asm("{ .reg .u64 t; cvta.to.shared.u64 t, %1; cvt.u32.u64 %0, t; }" : "=r"(a) : "l"(p));
    return a;
}
#define CPA16(dst, src) \
    asm volatile("cp.async.cg.shared.global [%0], [%1], 16;" :: "r"(dst), "l"(src) : "memory")
#define CP_COMMIT() asm volatile("cp.async.commit_group;" ::: "memory")
#define CP_WAIT0()  asm volatile("cp.async.wait_group 0;" ::: "memory")

#define LDSM4(r, addr) \
    asm volatile("ldmatrix.sync.aligned.m8n8.x4.shared.b16 {%0,%1,%2,%3}, [%4];" \
                 : "=r"((r)[0]), "=r"((r)[1]), "=r"((r)[2]), "=r"((r)[3]) : "r"(addr))
#define LDSM4T(r, addr) \
    asm volatile("ldmatrix.sync.aligned.m8n8.x4.trans.shared.b16 {%0,%1,%2,%3}, [%4];" \
                 : "=r"((r)[0]), "=r"((r)[1]), "=r"((r)[2]), "=r"((r)[3]) : "r"(addr))
#define MMA16816(c, a, b0, b1) \
    asm volatile("mma.sync.aligned.m16n8k16.row.col.f32.bf16.bf16.f32 " \
                 "{%0,%1,%2,%3}, {%4,%5,%6,%7}, {%8,%9}, {%0,%1,%2,%3};" \
                 : "+f"((c)[0]), "+f"((c)[1]), "+f"((c)[2]), "+f"((c)[3]) \
                 : "r"((a)[0]), "r"((a)[1]), "r"((a)[2]), "r"((a)[3]), "r"(b0), "r"(b1))

#define BAR_SYNC(id, cnt)   asm volatile("bar.sync %0, %1;"   :: "r"(id), "r"(cnt) : "memory")
#define BAR_ARRIVE(id, cnt) asm volatile("bar.arrive %0, %1;" :: "r"(id), "r"(cnt) : "memory")

// ---------------- zero the degree counters (graph replays need fresh zeros) ----------------
__global__ void zdeg_kernel() {
    g_degcnt[blockIdx.x * 1024 + threadIdx.x] = 0;
}

// ---------------- emb -> embT bf16 transpose: [b][i][d] -> [b][d][i] ----------------
__global__ void __launch_bounds__(256) embT_kernel(const float* __restrict__ emb) {
    __shared__ float tile[32][33];
    int b = blockIdx.z, i0 = blockIdx.x * 32, d0 = blockIdx.y * 32;
    int tx = threadIdx.x & 31, ty = threadIdx.x >> 5;
    const float* src = emb + ((size_t)b * N_ + i0) * D_ + d0;
#pragma unroll
    for (int k = 0; k < 4; ++k)
        tile[ty + 8 * k][tx] = src[(ty + 8 * k) * D_ + tx];
    __syncthreads();
    __nv_bfloat16* dst = (__nv_bfloat16*)g_embT + ((size_t)b * D_ + d0) * N_ + i0;
#pragma unroll
    for (int k = 0; k < 4; ++k)
        dst[(ty + 8 * k) * N_ + tx] = __float2bfloat16(tile[tx][ty + 8 * k]);
}

// ---------------- GEMM1 fused (warp-specialized):
//   snT[b][d][j] = sum_i cost[b,i,j]*emb[b,i,d]  +  degree counting
// CTA 128(d=M) x 64(j=N); warps 0-3 produce (LDG fp32 cost -> cvt bf16 -> STS,
// cp.async A, count nonzeros), warps 4-7 consume (ldmatrix + mma).
// smem: A0[0,16K) A1[16K,32K) B0[32K,40K) B1[40K,48K) cnt[48K,56K)
#define G1_SMEM 57344

__global__ void __launch_bounds__(256) gemm1_fused_kernel(const float* __restrict__ cost) {
    extern __shared__ char smem[];
    uint32_t sb = smem_to_u32(smem);
    int* cnt = (int*)(smem + 49152);
    const int t = threadIdx.x;
    const int b = blockIdx.y, j0 = blockIdx.x * 64;
    const float* costb = cost + (size_t)b * N_ * N_;
    const __nv_bfloat16* embTb = (const __nv_bfloat16*)g_embT + (size_t)b * D_ * N_;

    const int FULL0 = 1, FREE0 = 3, PBAR = 5;

    if (t < 128) {
        // ===================== PRODUCER =====================
        for (int k = t; k < 2048; k += 128) cnt[k] = 0;
        BAR_SYNC(PBAR, 128);
        const int lane = t & 31;
        const unsigned hm = 0xFFFFu << ((lane >> 4) * 16);
        const int rb = t >> 4;          // row base within 8-row group (0..7)
        const int c4 = t & 15;          // float4 column (0..15)

#pragma unroll 1
        for (int s = 0; s < 32; ++s) {
            const int buf = s & 1, i0 = s * 64;
            if (s >= 2) BAR_SYNC(FREE0 + buf, 256);
            const uint32_t ab = sb + buf * 16384;
            const uint32_t bb = sb + 32768 + buf * 8192;
            // A: embT bf16 tile [128 d][64 i], cp.async 16B x8
#pragma unroll
            for (int p = 0; p < 8; ++p) {
                int idx = t + p * 128;
                int row = idx >> 3, c = idx & 7;
                uint32_t dst = ab + row * 128 + ((c * 16) ^ ((row & 7) << 4));
                CPA16(dst, embTb + (size_t)row * N_ + i0 + c * 8);
            }
            CP_COMMIT();
            // B: cost fp32 [64 i][64 j] -> count + cvt -> bf16 smem
            float4 v[8];
#pragma unroll
            for (int q = 0; q < 8; ++q) {
                int row = q * 8 + rb;
                v[q] = *(const float4*)(costb + (size_t)(i0 + row) * N_ + j0 + c4 * 4);
            }
#pragma unroll
            for (int q = 0; q < 8; ++q) {
                int row = q * 8 + rb;
                int lc = (v[q].x != 0.0f) + (v[q].y != 0.0f) +
                         (v[q].z != 0.0f) + (v[q].w != 0.0f);
                int red = __reduce_add_sync(hm, lc);
                if ((lane & 15) == 0) atomicAdd(&cnt[i0 + row], red);
                uint32_t p0, p1;
                asm("cvt.rn.satfinite.bf16x2.f32 %0, %1, %2;" : "=r"(p0) : "f"(v[q].y), "f"(v[q].x));
                asm("cvt.rn.satfinite.bf16x2.f32 %0, %1, %2;" : "=r"(p1) : "f"(v[q].w), "f"(v[q].z));
                uint32_t off = (uint32_t)c4 * 8;
                uint32_t dst = bb + row * 128 +
                               (((off & 0xFFF0u) ^ ((row & 7) << 4)) | (off & 8u));
                asm volatile("st.shared.v2.b32 [%0], {%1,%2};" :: "r"(dst), "r"(p0), "r"(p1) : "memory");
            }
            CP_WAIT0();
            BAR_ARRIVE(FULL0 + buf, 256);
        }
        // flush partial degree counts
        BAR_SYNC(PBAR, 128);
        int* gd = g_degcnt + b * N_;
        for (int k = t; k < 2048; k += 128)
            atomicAdd(&gd[k], cnt[k]);
    } else {
        // ===================== CONSUMER =====================
        const int tc = t - 128, w = tc >> 5, l = tc & 31;
        const int wm = (w & 1) * 64;        // d offset of warp (M)
        const int wn = (w >> 1) * 32;       // j offset of warp (N)
        const int lq = l & 15, lh = l >> 4;
        const uint32_t sx = (uint32_t)(l & 7) << 4;

        float acc[4][4][4];
#pragma unroll
        for (int mt = 0; mt < 4; ++mt)
#pragma unroll
            for (int n8 = 0; n8 < 4; ++n8)
#pragma unroll
                for (int r = 0; r < 4; ++r) acc[mt][n8][r] = 0.0f;

#pragma unroll 1
        for (int s = 0; s < 32; ++s) {
            const int buf = s & 1;
            BAR_SYNC(FULL0 + buf, 256);
            const uint32_t abase = sb + buf * 16384;
            const uint32_t bbase = sb + 32768 + buf * 8192;
#pragma unroll
            for (int ks = 0; ks < 4; ++ks) {
                uint32_t a[4][4], bf[2][4];
#pragma unroll
                for (int mt = 0; mt < 4; ++mt) {
                    uint32_t addr = abase + (uint32_t)(wm + mt * 16 + lq) * 128 +
                                    (((uint32_t)(ks * 32 + lh * 16)) ^ sx);
                    LDSM4(a[mt], addr);
                }
#pragma unroll
                for (int nt = 0; nt < 2; ++nt) {
                    uint32_t addr = bbase + (uint32_t)(ks * 16 + lq) * 128 +
                                    (((uint32_t)((wn + nt * 16 + lh * 8) * 2)) ^ sx);
                    LDSM4T(bf[nt], addr);
                }
#pragma unroll
                for (int mt = 0; mt < 4; ++mt)
#pragma unroll
                    for (int nt = 0; nt < 2; ++nt) {
                        MMA16816(acc[mt][2 * nt],     a[mt], bf[nt][0], bf[nt][1]);
                        MMA16816(acc[mt][2 * nt + 1], a[mt], bf[nt][2], bf[nt][3]);
                    }
            }
            if (s < 30) BAR_ARRIVE(FREE0 + buf, 256);
        }

        // epilogue: acc -> g_snT[b][d][j]
        float* dstb = g_snT + (size_t)b * D_ * N_;
        const int mrow = wm + (l >> 2);
        const int jcol = j0 + wn + (l & 3) * 2;
#pragma unroll
        for (int mt = 0; mt < 4; ++mt) {
#pragma unroll
            for (int n8 = 0; n8 < 4; ++n8) {
                int m = mrow + mt * 16;
                int j = jcol + n8 * 8;
                *(float2*)&dstb[(size_t)m * N_ + j] =
                    make_float2(acc[mt][n8][0], acc[mt][n8][1]);
                *(float2*)&dstb[(size_t)(m + 8) * N_ + j] =
                    make_float2(acc[mt][n8][2], acc[mt][n8][3]);
            }
        }
    }
}

// ---------------- packed f32x2 helpers (FFMA2, for GEMM2) ----------------
__device__ __forceinline__ unsigned long long pk2(float x, float y) {
    unsigned long long r;
    asm("mov.b64 %0, {%1, %2};" : "=l"(r) : "f"(x), "f"(y));
    return r;
}
__device__ __forceinline__ void fma2(unsigned long long& d, unsigned long long a,
                                     unsigned long long b) {
    asm("fma.rn.f32x2 %0, %1, %2, %0;" : "+l"(d) : "l"(a), "l"(b));
}
__device__ __forceinline__ void upk2(unsigned long long v, float& x, float& y) {
    asm("mov.b64 {%0, %1}, %2;" : "=f"(x), "=f"(y) : "l"(v));
}

// ---------------- GEMM2: out = relu([emb | snT/deg] @ W^T + b) ----------------
// CTA 64(M) x 128(N), 256 threads, thread tile m8 x n4 via f32x2. grid = 256.
#define PAD2A 68
#define PAD2W 132
__global__ void __launch_bounds__(256) gemm2_kernel(const float* __restrict__ emb,
                                                    const float* __restrict__ Wp,
                                                    const float* __restrict__ bias,
                                                    float* __restrict__ out) {
    __shared__ float As[2][16][PAD2A];
    __shared__ float Ws[2][16][PAD2W];
    __shared__ float invs[64];

    const int b  = blockIdx.y;
    const int r0 = blockIdx.x * 64;
    const int t  = threadIdx.x;
    const float* embb = emb + ((size_t)b * N_ + r0) * D_;

    const int tm = (t & 7) * 8;     // 0..56 (rows)
    const int tn = (t >> 3) * 4;    // 0..124 (cols)

    unsigned long long acc[8][2];
#pragma unroll
    for (int m = 0; m < 8; ++m) { acc[m][0] = 0ull; acc[m][1] = 0ull; }

    if (t < 64) invs[t] = 1.0f / (float)g_degcnt[b * N_ + r0 + t];

    const int ml = t >> 2;          // 0..63
    const int ql = (t & 3) * 4;     // 0,4,8,12
    const int kk = t >> 4;          // 0..15
    const int m4 = (t & 15) * 4;    // 0..60

#define G2_LOAD(BUF, K0)                                                          \
    {                                                                             \
        if ((K0) < 128) {                                                         \
            float4 v = *(const float4*)(embb + (size_t)ml * D_ + (K0) + ql);      \
            As[BUF][ql + 0][ml] = v.x; As[BUF][ql + 1][ml] = v.y;                 \
            As[BUF][ql + 2][ml] = v.z; As[BUF][ql + 3][ml] = v.w;                 \
        } else {                                                                  \
            const float* srow = g_snT + ((size_t)b * D_ + ((K0) - 128 + kk)) * N_ \
                                + r0 + m4;                                        \
            float4 v = *(const float4*)srow;                                      \
            v.x *= invs[m4 + 0]; v.y *= invs[m4 + 1];                             \
            v.z *= invs[m4 + 2]; v.w *= invs[m4 + 3];                             \
            *(float4*)&As[BUF][kk][m4] = v;                                       \
        }                                                                         \
        float4 w0 = *(const float4*)(Wp + (size_t)ml * 256 + (K0) + ql);          \
        Ws[BUF][ql + 0][ml] = w0.x; Ws[BUF][ql + 1][ml] = w0.y;                   \
        Ws[BUF][ql + 2][ml] = w0.z; Ws[BUF][ql + 3][ml] = w0.w;                   \
        float4 w1 = *(const float4*)(Wp + (size_t)(ml + 64) * 256 + (K0) + ql);   \
        Ws[BUF][ql + 0][ml + 64] = w1.x; Ws[BUF][ql + 1][ml + 64] = w1.y;         \
        Ws[BUF][ql + 2][ml + 64] = w1.z; Ws[BUF][ql + 3][ml + 64] = w1.w;         \
    }

    G2_LOAD(0, 0);
    __syncthreads();

#pragma unroll 1
    for (int s = 0; s < 16; ++s) {
        const int buf = s & 1;
        if (s + 1 < 16) { G2_LOAD(buf ^ 1, (s + 1) * 16); }
#pragma unroll
        for (int k = 0; k < 16; ++k) {
            float4 a0 = *(const float4*)&As[buf][k][tm];
            float4 a1 = *(const float4*)&As[buf][k][tm + 4];
            float4 w0 = *(const float4*)&Ws[buf][k][tn];
            unsigned long long ap[8], bp[2];
            ap[0] = pk2(a0.x, a0.x); ap[1] = pk2(a0.y, a0.y);
            ap[2] = pk2(a0.z, a0.z); ap[3] = pk2(a0.w, a0.w);
            ap[4] = pk2(a1.x, a1.x); ap[5] = pk2(a1.y, a1.y);
            ap[6] = pk2(a1.z, a1.z); ap[7] = pk2(a1.w, a1.w);
            bp[0] = pk2(w0.x, w0.y); bp[1] = pk2(w0.z, w0.w);
#pragma unroll
            for (int m = 0; m < 8; ++m) {
                fma2(acc[m][0], ap[m], bp[0]);
                fma2(acc[m][1], ap[m], bp[1]);
            }
        }
        __syncthreads();
    }

    float bv[4];
#pragma unroll
    for (int i = 0; i < 4; ++i) bv[i] = bias[tn + i];

    float* outb = out + ((size_t)b * N_ + r0) * D_;
#pragma unroll
    for (int m = 0; m < 8; ++m) {
        float x0, x1, x2, x3;
        upk2(acc[m][0], x0, x1);
        upk2(acc[m][1], x2, x3);
        float4 o;
        o.x = fmaxf(x0 + bv[0], 0.0f);
        o.y = fmaxf(x1 + bv[1], 0.0f);
        o.z = fmaxf(x2 + bv[2], 0.0f);
        o.w = fmaxf(x3 + bv[3], 0.0f);
        *(float4*)&outb[(size_t)(tm + m) * D_ + tn] = o;
    }
}

// ---------------- launch ----------------
extern "C" void kernel_launch(void* const* d_in, const int* in_sizes, int n_in,
                              void* d_out, int out_size) {
    const float* emb  = (const float*)d_in[0];   // [8, 2048, 128]
    const float* cost = (const float*)d_in[1];   // [8, 2048, 2048]
    const float* W    = (const float*)d_in[2];   // [128, 256]
    const float* bias = (const float*)d_in[3];   // [128]
    float* out = (float*)d_out;                  // [8, 2048, 128]

    zdeg_kernel<<<(B_ * N_) / 1024, 1024>>>();
    embT_kernel<<<dim3(N_ / 32, D_ / 32, B_), 256>>>(emb);

    cudaFuncSetAttribute(gemm1_fused_kernel,
                         cudaFuncAttributeMaxDynamicSharedMemorySize, G1_SMEM);
    gemm1_fused_kernel<<<dim3(N_ / 64, B_), 256, G1_SMEM>>>(cost);

    gemm2_kernel<<<dim3(N_ / 64, B_), 256>>>(emb, W, bias, out);
}

// round 12
// speedup vs baseline: 1.3110x; 1.3110x over previous
#include <cuda_runtime.h>
#include <cuda_bf16.h>
#include <cstdint>

#define B_ 8
#define N_ 2048
#define D_ 128

// ---------------- scratch (__device__ globals: allocation-free) ----------------
__device__ __align__(16) unsigned int g_costb16[(size_t)B_ * N_ * N_ / 2]; // bf16 [b][i][j]
__device__ __align__(16) unsigned int g_embT[(size_t)B_ * D_ * N_ / 2];    // bf16 [b][d][i]
__device__ __align__(16) float g_snT[(size_t)B_ * D_ * N_];                // fp32 [b][d][j]
__device__ float g_invdeg[B_ * N_];

// ---------------- helpers ----------------
__device__ __forceinline__ uint32_t smem_to_u32(const void* p) {
    uint32_t a;
    asm("{ .reg .u64 t; cvta.to.shared.u64 t, %1; cvt.u32.u64 %0, t; }" : "=r"(a) : "l"(p));
    return a;
}
#define CPA16(dst, src) \
    asm volatile("cp.async.cg.shared.global [%0], [%1], 16;" :: "r"(dst), "l"(src) : "memory")
#define CP_COMMIT() asm volatile("cp.async.commit_group;" ::: "memory")
#define CP_WAIT(n)  asm volatile("cp.async.wait_group %0;" :: "n"(n) : "memory")

#define LDSM4(r, addr) \
    asm volatile("ldmatrix.sync.aligned.m8n8.x4.shared.b16 {%0,%1,%2,%3}, [%4];" \
                 : "=r"((r)[0]), "=r"((r)[1]), "=r"((r)[2]), "=r"((r)[3]) : "r"(addr))
#define LDSM4T(r, addr) \
    asm volatile("ldmatrix.sync.aligned.m8n8.x4.trans.shared.b16 {%0,%1,%2,%3}, [%4];" \
                 : "=r"((r)[0]), "=r"((r)[1]), "=r"((r)[2]), "=r"((r)[3]) : "r"(addr))
#define MMA16816(c, a, b0, b1) \
    asm volatile("mma.sync.aligned.m16n8k16.row.col.f32.bf16.bf16.f32 " \
                 "{%0,%1,%2,%3}, {%4,%5,%6,%7}, {%8,%9}, {%0,%1,%2,%3};" \
                 : "+f"((c)[0]), "+f"((c)[1]), "+f"((c)[2]), "+f"((c)[3]) \
                 : "r"((a)[0]), "r"((a)[1]), "r"((a)[2]), "r"((a)[3]), "r"(b0), "r"(b1))

// ---------------- degree + fp32->bf16 cost conversion (fused single pass) ----------------
__global__ void __launch_bounds__(256) degconv_kernel(const float* __restrict__ cost) {
    int row  = blockIdx.x * 8 + (threadIdx.x >> 5);
    int lane = threadIdx.x & 31;
    const float4* r4 = (const float4*)(cost + (size_t)row * N_);
    unsigned int* w = g_costb16 + (size_t)row * (N_ / 2);
    int cnt = 0;
#pragma unroll
    for (int it = 0; it < 16; ++it) {
        float4 v = r4[it * 32 + lane];
        cnt += (v.x != 0.0f) + (v.y != 0.0f) + (v.z != 0.0f) + (v.w != 0.0f);
        unsigned int p0, p1;
        asm("cvt.rn.satfinite.bf16x2.f32 %0, %1, %2;" : "=r"(p0) : "f"(v.y), "f"(v.x));
        asm("cvt.rn.satfinite.bf16x2.f32 %0, %1, %2;" : "=r"(p1) : "f"(v.w), "f"(v.z));
        *(uint2*)&w[it * 64 + lane * 2] = make_uint2(p0, p1);
    }
#pragma unroll
    for (int off = 16; off > 0; off >>= 1)
        cnt += __shfl_down_sync(0xffffffffu, cnt, off);
    if (lane == 0) g_invdeg[row] = 1.0f / (float)cnt;
}

// ---------------- emb -> embT bf16 transpose: [b][i][d] -> [b][d][i] ----------------
__global__ void __launch_bounds__(256) embT_kernel(const float* __restrict__ emb) {
    __shared__ float tile[32][33];
    int b = blockIdx.z, i0 = blockIdx.x * 32, d0 = blockIdx.y * 32;
    int tx = threadIdx.x & 31, ty = threadIdx.x >> 5;
    const float* src = emb + ((size_t)b * N_ + i0) * D_ + d0;
#pragma unroll
    for (int k = 0; k < 4; ++k)
        tile[ty + 8 * k][tx] = src[(ty + 8 * k) * D_ + tx];
    __syncthreads();
    __nv_bfloat16* dst = (__nv_bfloat16*)g_embT + ((size_t)b * D_ + d0) * N_ + i0;
#pragma unroll
    for (int k = 0; k < 4; ++k)
        dst[(ty + 8 * k) * N_ + tx] = __float2bfloat16(tile[tx][ty + 8 * k]);
}

// ---------------- GEMM1 (mma.sync bf16): snT[b][d][j] = sum_i cost[b,i,j]*emb[b,i,d]
// CTA 128(d=M) x 128(j=N); 8 warps of 64x32 (2Mx4N); K=i in 64-wide
// double-buffered cp.async stages. A [128][64] bf16 rows 128B, B [64][128] rows 256B.
// Addressing identical to the validated round-3 kernel; only warp count changed.
#define G1_STAGE 32768   // A 16KB + B 16KB
#define G1_SMEM  (2 * G1_STAGE)

__device__ __forceinline__ void g1_load(uint32_t sb, int st,
                                        const __nv_bfloat16* __restrict__ costb,
                                        const __nv_bfloat16* __restrict__ embTb,
                                        int i0, int j0, int t) {
    uint32_t abase = sb + st * G1_STAGE;
    uint32_t bbase = abase + 16384;
#pragma unroll
    for (int p = 0; p < 4; ++p) {           // A: 128 rows x 8 x 16B = 1024 chunks
        int ca = t + p * 256;
        int row = ca >> 3, c = ca & 7;
        uint32_t dst = abase + row * 128 + ((c * 16) ^ ((row & 7) << 4));
        CPA16(dst, embTb + (size_t)row * N_ + i0 + c * 8);
    }
#pragma unroll
    for (int p = 0; p < 4; ++p) {           // B: 64 rows x 16 x 16B = 1024 chunks
        int cb = t + p * 256;
        int row = cb >> 4, jc = cb & 15;
        uint32_t dst = bbase + row * 256 + ((jc * 16) ^ ((row & 7) << 4));
        CPA16(dst, costb + (size_t)(i0 + row) * N_ + j0 + jc * 8);
    }
}

__global__ void __launch_bounds__(256) gemm1_mma_kernel() {
    extern __shared__ char smem[];
    uint32_t sb = smem_to_u32(smem);
    const int t = threadIdx.x, wid = t >> 5, l = t & 31;
    const int b = blockIdx.y, j0 = blockIdx.x * 128;
    const __nv_bfloat16* costb = (const __nv_bfloat16*)g_costb16 + (size_t)b * N_ * N_;
    const __nv_bfloat16* embTb = (const __nv_bfloat16*)g_embT + (size_t)b * D_ * N_;

    const int wm = (wid & 1) * 64;          // d offset of warp (M: 2 warps)
    const int wn = (wid >> 1) * 32;         // j offset of warp (N: 4 warps)
    const int lq = l & 15, lh = l >> 4;
    const uint32_t sx = (uint32_t)(l & 7) << 4;

    float acc[4][4][4];
#pragma unroll
    for (int mt = 0; mt < 4; ++mt)
#pragma unroll
        for (int n8 = 0; n8 < 4; ++n8)
#pragma unroll
            for (int r = 0; r < 4; ++r) acc[mt][n8][r] = 0.0f;

    g1_load(sb, 0, costb, embTb, 0, j0, t);
    CP_COMMIT();

#pragma unroll 1
    for (int c = 0; c < 32; ++c) {
        if (c + 1 < 32) {
            g1_load(sb, (c + 1) & 1, costb, embTb, (c + 1) * 64, j0, t);
            CP_COMMIT();
            CP_WAIT(1);
        } else {
            CP_WAIT(0);
        }
        __syncthreads();

        uint32_t abase = sb + (c & 1) * G1_STAGE;
        uint32_t bbase = abase + 16384;
#pragma unroll
        for (int ks = 0; ks < 4; ++ks) {
            uint32_t a[4][4], bf[2][4];
#pragma unroll
            for (int mt = 0; mt < 4; ++mt) {
                uint32_t addr = abase + (uint32_t)(wm + mt * 16 + lq) * 128 +
                                (((uint32_t)(ks * 32 + lh * 16)) ^ sx);
                LDSM4(a[mt], addr);
            }
#pragma unroll
            for (int nt = 0; nt < 2; ++nt) {
                uint32_t addr = bbase + (uint32_t)(ks * 16 + lq) * 256 +
                                (((uint32_t)((wn + nt * 16 + lh * 8) * 2)) ^ sx);
                LDSM4T(bf[nt], addr);
            }
#pragma unroll
            for (int mt = 0; mt < 4; ++mt)
#pragma unroll
                for (int nt = 0; nt < 2; ++nt) {
                    MMA16816(acc[mt][2 * nt],     a[mt], bf[nt][0], bf[nt][1]);
                    MMA16816(acc[mt][2 * nt + 1], a[mt], bf[nt][2], bf[nt][3]);
                }
        }
        __syncthreads();
    }

    // epilogue: acc -> g_snT[b][d][j]
    float* dstb = g_snT + (size_t)b * D_ * N_;
    const int mrow = wm + (l >> 2);
    const int jcol = j0 + wn + (l & 3) * 2;
#pragma unroll
    for (int mt = 0; mt < 4; ++mt) {
#pragma unroll
        for (int n8 = 0; n8 < 4; ++n8) {
            int m = mrow + mt * 16;
            int j = jcol + n8 * 8;
            *(float2*)&dstb[(size_t)m * N_ + j] =
                make_float2(acc[mt][n8][0], acc[mt][n8][1]);
            *(float2*)&dstb[(size_t)(m + 8) * N_ + j] =
                make_float2(acc[mt][n8][2], acc[mt][n8][3]);
        }
    }
}

// ---------------- packed f32x2 helpers (FFMA2, for GEMM2) ----------------
__device__ __forceinline__ unsigned long long pk2(float x, float y) {
    unsigned long long r;
    asm("mov.b64 %0, {%1, %2};" : "=l"(r) : "f"(x), "f"(y));
    return r;
}
__device__ __forceinline__ void fma2(unsigned long long& d, unsigned long long a,
                                     unsigned long long b) {
    asm("fma.rn.f32x2 %0, %1, %2, %0;" : "+l"(d) : "l"(a), "l"(b));
}
__device__ __forceinline__ void upk2(unsigned long long v, float& x, float& y) {
    asm("mov.b64 {%0, %1}, %2;" : "=f"(x), "=f"(y) : "l"(v));
}

// ---------------- GEMM2: out = relu([emb | snT/deg] @ W^T + b) ----------------
// CTA 64(M) x 128(N), 128 threads, thread tile 8x8 (keeps the round-3 LDS:FMA
// ratio that round-8 proved critical), grid 256 for full SM coverage.
#define PAD2A 68
#define PAD2W 132
__global__ void __launch_bounds__(128) gemm2_kernel(const float* __restrict__ emb,
                                                    const float* __restrict__ Wp,
                                                    const float* __restrict__ bias,
                                                    float* __restrict__ out) {
    __shared__ float As[2][16][PAD2A];
    __shared__ float Ws[2][16][PAD2W];
    __shared__ float invs[64];

    const int b  = blockIdx.y;
    const int r0 = blockIdx.x * 64;
    const int t  = threadIdx.x;
    const float* embb = emb + ((size_t)b * N_ + r0) * D_;

    const int tm = (t & 7) * 8;     // rows 0..56
    const int tn = (t >> 3) * 8;    // cols 0..120

    unsigned long long acc[8][4];
#pragma unroll
    for (int m = 0; m < 8; ++m)
#pragma unroll
        for (int p = 0; p < 4; ++p) acc[m][p] = 0ull;

    if (t < 64) invs[t] = g_invdeg[b * N_ + r0 + t];

#define G2_LOAD(BUF, K0)                                                          \
    {                                                                             \
        if ((K0) < 128) {                                                         \
            _Pragma("unroll")                                                     \
            for (int p = 0; p < 2; ++p) {                                         \
                int fid = t + p * 128;                                            \
                int m = fid >> 2, q = (fid & 3) * 4;                              \
                float4 v = *(const float4*)(embb + (size_t)m * D_ + (K0) + q);    \
                As[BUF][q + 0][m] = v.x; As[BUF][q + 1][m] = v.y;                 \
                As[BUF][q + 2][m] = v.z; As[BUF][q + 3][m] = v.w;                 \
            }                                                                     \
        } else {                                                                  \
            _Pragma("unroll")                                                     \
            for (int p = 0; p < 2; ++p) {                                         \
                int fid = t + p * 128;                                            \
                int kk = fid >> 4, mc = (fid & 15) * 4;                           \
                const float* srow = g_snT + ((size_t)b * D_ + ((K0) - 128 + kk)) * N_ \
                                    + r0 + mc;                                    \
                float4 v = *(const float4*)srow;                                  \
                v.x *= invs[mc + 0]; v.y *= invs[mc + 1];                         \
                v.z *= invs[mc + 2]; v.w *= invs[mc + 3];                         \
                *(float4*)&As[BUF][kk][mc] = v;                                   \
            }                                                                     \
        }                                                                         \
        _Pragma("unroll")                                                         \
        for (int p = 0; p < 4; ++p) {                                             \
            int fid = t + p * 128;                                                \
            int dn = fid >> 2, q = (fid & 3) * 4;                                 \
            float4 w = *(const float4*)(Wp + (size_t)dn * 256 + (K0) + q);        \
            Ws[BUF][q + 0][dn] = w.x; Ws[BUF][q + 1][dn] = w.y;                   \
            Ws[BUF][q + 2][dn] = w.z; Ws[BUF][q + 3][dn] = w.w;                   \
        }                                                                         \
    }

    G2_LOAD(0, 0);
    __syncthreads();

#pragma unroll 1
    for (int s = 0; s < 16; ++s) {
        const int buf = s & 1;
        if (s + 1 < 16) { G2_LOAD(buf ^ 1, (s + 1) * 16); }
#pragma unroll
        for (int k = 0; k < 16; ++k) {
            float4 a0 = *(const float4*)&As[buf][k][tm];
            float4 a1 = *(const float4*)&As[buf][k][tm + 4];
            float4 w0 = *(const float4*)&Ws[buf][k][tn];
            float4 w1 = *(const float4*)&Ws[buf][k][tn + 4];
            unsigned long long ap[8], bp[4];
            ap[0] = pk2(a0.x, a0.x); ap[1] = pk2(a0.y, a0.y);
            ap[2] = pk2(a0.z, a0.z); ap[3] = pk2(a0.w, a0.w);
            ap[4] = pk2(a1.x, a1.x); ap[5] = pk2(a1.y, a1.y);
            ap[6] = pk2(a1.z, a1.z); ap[7] = pk2(a1.w, a1.w);
            bp[0] = pk2(w0.x, w0.y); bp[1] = pk2(w0.z, w0.w);
            bp[2] = pk2(w1.x, w1.y); bp[3] = pk2(w1.z, w1.w);
#pragma unroll
            for (int m = 0; m < 8; ++m)
#pragma unroll
                for (int p = 0; p < 4; ++p) fma2(acc[m][p], ap[m], bp[p]);
        }
        __syncthreads();
    }

    float bv[8];
#pragma unroll
    for (int i = 0; i < 8; ++i) bv[i] = bias[tn + i];

    float* outb = out + ((size_t)b * N_ + r0) * D_;
#pragma unroll
    for (int m = 0; m < 8; ++m) {
#pragma unroll
        for (int p = 0; p < 4; ++p) {
            float lo, hi;
            upk2(acc[m][p], lo, hi);
            lo = fmaxf(lo + bv[p * 2], 0.0f);
            hi = fmaxf(hi + bv[p * 2 + 1], 0.0f);
            *(float2*)&outb[(size_t)(tm + m) * D_ + tn + p * 2] = make_float2(lo, hi);
        }
    }
}

// ---------------- launch ----------------
extern "C" void kernel_launch(void* const* d_in, const int* in_sizes, int n_in,
                              void* d_out, int out_size) {
    const float* emb  = (const float*)d_in[0];   // [8, 2048, 128]
    const float* cost = (const float*)d_in[1];   // [8, 2048, 2048]
    const float* W    = (const float*)d_in[2];   // [128, 256]
    const float* bias = (const float*)d_in[3];   // [128]
    float* out = (float*)d_out;                  // [8, 2048, 128]

    degconv_kernel<<<(B_ * N_) / 8, 256>>>(cost);
    embT_kernel<<<dim3(N_ / 32, D_ / 32, B_), 256>>>(emb);

    cudaFuncSetAttribute(gemm1_mma_kernel,
                         cudaFuncAttributeMaxDynamicSharedMemorySize, G1_SMEM);
    gemm1_mma_kernel<<<dim3(N_ / 128, B_), 256, G1_SMEM>>>();

    gemm2_kernel<<<dim3(N_ / 64, B_), 128>>>(emb, W, bias, out);
}

// round 14
// speedup vs baseline: 1.5061x; 1.1488x over previous
#include <cuda_runtime.h>
#include <cuda_bf16.h>
#include <cstdint>

#define B_ 8
#define N_ 2048
#define D_ 128

// ---------------- scratch (__device__ globals: allocation-free) ----------------
__device__ __align__(16) unsigned int g_costb16[(size_t)B_ * N_ * N_ / 2]; // bf16 [b][i][j]
__device__ __align__(16) unsigned int g_embT[(size_t)B_ * D_ * N_ / 2];    // bf16 [b][d][i]
__device__ __align__(16) float g_sn[(size_t)B_ * N_ * D_];                 // fp32 [b][j][d]
__device__ __align__(16) __nv_bfloat16 g_Whi[D_ * 2 * D_];                 // bf16 [n][k]
__device__ __align__(16) __nv_bfloat16 g_Wlo[D_ * 2 * D_];                 // bf16 [n][k]
__device__ float g_invdeg[B_ * N_];

// ---------------- helpers ----------------
__device__ __forceinline__ uint32_t smem_to_u32(const void* p) {
    uint32_t a;
    asm("{ .reg .u64 t; cvta.to.shared.u64 t, %1; cvt.u32.u64 %0, t; }" : "=r"(a) : "l"(p));
    return a;
}
#define CPA16(dst, src) \
    asm volatile("cp.async.cg.shared.global [%0], [%1], 16;" :: "r"(dst), "l"(src) : "memory")
#define CP_COMMIT() asm volatile("cp.async.commit_group;" ::: "memory")
#define CP_WAIT(n)  asm volatile("cp.async.wait_group %0;" :: "n"(n) : "memory")

#define LDSM4(r, addr) \
    asm volatile("ldmatrix.sync.aligned.m8n8.x4.shared.b16 {%0,%1,%2,%3}, [%4];" \
                 : "=r"((r)[0]), "=r"((r)[1]), "=r"((r)[2]), "=r"((r)[3]) : "r"(addr))
#define LDSM4T(r, addr) \
    asm volatile("ldmatrix.sync.aligned.m8n8.x4.trans.shared.b16 {%0,%1,%2,%3}, [%4];" \
                 : "=r"((r)[0]), "=r"((r)[1]), "=r"((r)[2]), "=r"((r)[3]) : "r"(addr))
#define MMA16816(c, a, b0, b1) \
    asm volatile("mma.sync.aligned.m16n8k16.row.col.f32.bf16.bf16.f32 " \
                 "{%0,%1,%2,%3}, {%4,%5,%6,%7}, {%8,%9}, {%0,%1,%2,%3};" \
                 : "+f"((c)[0]), "+f"((c)[1]), "+f"((c)[2]), "+f"((c)[3]) \
                 : "r"((a)[0]), "r"((a)[1]), "r"((a)[2]), "r"((a)[3]), "r"(b0), "r"(b1))

// ---------------- degree + fp32->bf16 cost conversion (fused single pass) ----------------
__global__ void __launch_bounds__(256) degconv_kernel(const float* __restrict__ cost) {
    int row  = blockIdx.x * 8 + (threadIdx.x >> 5);
    int lane = threadIdx.x & 31;
    const float4* r4 = (const float4*)(cost + (size_t)row * N_);
    unsigned int* w = g_costb16 + (size_t)row * (N_ / 2);
    int cnt = 0;
#pragma unroll
    for (int it = 0; it < 16; ++it) {
        float4 v = r4[it * 32 + lane];
        cnt += (v.x != 0.0f) + (v.y != 0.0f) + (v.z != 0.0f) + (v.w != 0.0f);
        unsigned int p0, p1;
        asm("cvt.rn.satfinite.bf16x2.f32 %0, %1, %2;" : "=r"(p0) : "f"(v.y), "f"(v.x));
        asm("cvt.rn.satfinite.bf16x2.f32 %0, %1, %2;" : "=r"(p1) : "f"(v.w), "f"(v.z));
        *(uint2*)&w[it * 64 + lane * 2] = make_uint2(p0, p1);
    }
#pragma unroll
    for (int off = 16; off > 0; off >>= 1)
        cnt += __shfl_down_sync(0xffffffffu, cnt, off);
    if (lane == 0) g_invdeg[row] = 1.0f / (float)cnt;
}

// ---------------- emb -> embT bf16 transpose: [b][i][d] -> [b][d][i] ----------------
__global__ void __launch_bounds__(256) embT_kernel(const float* __restrict__ emb) {
    __shared__ float tile[32][33];
    int b = blockIdx.z, i0 = blockIdx.x * 32, d0 = blockIdx.y * 32;
    int tx = threadIdx.x & 31, ty = threadIdx.x >> 5;
    const float* src = emb + ((size_t)b * N_ + i0) * D_ + d0;
#pragma unroll
    for (int k = 0; k < 4; ++k)
        tile[ty + 8 * k][tx] = src[(ty + 8 * k) * D_ + tx];
    __syncthreads();
    __nv_bfloat16* dst = (__nv_bfloat16*)g_embT + ((size_t)b * D_ + d0) * N_ + i0;
#pragma unroll
    for (int k = 0; k < 4; ++k)
        dst[(ty + 8 * k) * N_ + tx] = __float2bfloat16(tile[tx][ty + 8 * k]);
}

// ---------------- W split: Whi = bf16(W), Wlo = bf16(W - Whi) ----------------
__global__ void wsplit_kernel(const float* __restrict__ W) {
    int i = blockIdx.x * 256 + threadIdx.x;   // 128 blocks x 256 = 32768
    float w = W[i];
    __nv_bfloat16 h = __float2bfloat16(w);
    g_Whi[i] = h;
    g_Wlo[i] = __float2bfloat16(w - __bfloat162float(h));
}

// ---------------- GEMM1 (mma.sync bf16): sn[b][j][d] = sum_i cost[b,i,j]*emb[b,i,d]
// CTA 128(d=M) x 128(j=N); 8 warps of 64x32 (2Mx4N); K=i in 64-wide
// double-buffered cp.async stages. Addressing validated rounds 3/9/12.
#define G1_STAGE 32768   // A 16KB + B 16KB
#define G1_SMEM  (2 * G1_STAGE)

__device__ __forceinline__ void g1_load(uint32_t sb, int st,
                                        const __nv_bfloat16* __restrict__ costb,
                                        const __nv_bfloat16* __restrict__ embTb,
                                        int i0, int j0, int t) {
    uint32_t abase = sb + st * G1_STAGE;
    uint32_t bbase = abase + 16384;
#pragma unroll
    for (int p = 0; p < 4; ++p) {           // A: 128 rows x 8 x 16B = 1024 chunks
        int ca = t + p * 256;
        int row = ca >> 3, c = ca & 7;
        uint32_t dst = abase + row * 128 + ((c * 16) ^ ((row & 7) << 4));
        CPA16(dst, embTb + (size_t)row * N_ + i0 + c * 8);
    }
#pragma unroll
    for (int p = 0; p < 4; ++p) {           // B: 64 rows x 16 x 16B = 1024 chunks
        int cb = t + p * 256;
        int row = cb >> 4, jc = cb & 15;
        uint32_t dst = bbase + row * 256 + ((jc * 16) ^ ((row & 7) << 4));
        CPA16(dst, costb + (size_t)(i0 + row) * N_ + j0 + jc * 8);
    }
}

__global__ void __launch_bounds__(256) gemm1_mma_kernel() {
    extern __shared__ char smem[];
    uint32_t sb = smem_to_u32(smem);
    const int t = threadIdx.x, wid = t >> 5, l = t & 31;
    const int b = blockIdx.y, j0 = blockIdx.x * 128;
    const __nv_bfloat16* costb = (const __nv_bfloat16*)g_costb16 + (size_t)b * N_ * N_;
    const __nv_bfloat16* embTb = (const __nv_bfloat16*)g_embT + (size_t)b * D_ * N_;

    const int wm = (wid & 1) * 64;          // d offset of warp (M: 2 warps)
    const int wn = (wid >> 1) * 32;         // j offset of warp (N: 4 warps)
    const int lq = l & 15, lh = l >> 4;
    const uint32_t sx = (uint32_t)(l & 7) << 4;

    float acc[4][4][4];
#pragma unroll
    for (int mt = 0; mt < 4; ++mt)
#pragma unroll
        for (int n8 = 0; n8 < 4; ++n8)
#pragma unroll
            for (int r = 0; r < 4; ++r) acc[mt][n8][r] = 0.0f;

    g1_load(sb, 0, costb, embTb, 0, j0, t);
    CP_COMMIT();

#pragma unroll 1
    for (int c = 0; c < 32; ++c) {
        if (c + 1 < 32) {
            g1_load(sb, (c + 1) & 1, costb, embTb, (c + 1) * 64, j0, t);
            CP_COMMIT();
            CP_WAIT(1);
        } else {
            CP_WAIT(0);
        }
        __syncthreads();

        uint32_t abase = sb + (c & 1) * G1_STAGE;
        uint32_t bbase = abase + 16384;
#pragma unroll
        for (int ks = 0; ks < 4; ++ks) {
            uint32_t a[4][4], bf[2][4];
#pragma unroll
            for (int mt = 0; mt < 4; ++mt) {
                uint32_t addr = abase + (uint32_t)(wm + mt * 16 + lq) * 128 +
                                (((uint32_t)(ks * 32 + lh * 16)) ^ sx);
                LDSM4(a[mt], addr);
            }
#pragma unroll
            for (int nt = 0; nt < 2; ++nt) {
                uint32_t addr = bbase + (uint32_t)(ks * 16 + lq) * 256 +
                                (((uint32_t)((wn + nt * 16 + lh * 8) * 2)) ^ sx);
                LDSM4T(bf[nt], addr);
            }
#pragma unroll
            for (int mt = 0; mt < 4; ++mt)
#pragma unroll
                for (int nt = 0; nt < 2; ++nt) {
                    MMA16816(acc[mt][2 * nt],     a[mt], bf[nt][0], bf[nt][1]);
                    MMA16816(acc[mt][2 * nt + 1], a[mt], bf[nt][2], bf[nt][3]);
                }
        }
        __syncthreads();
    }

    // epilogue: acc (m=d, n=j) -> g_sn[b][j][d]  (row-major for gemm2's A loads)
    float* snb = g_sn + (size_t)b * N_ * D_;
    const int d0 = wm + (l >> 2);
    const int jc = j0 + wn + (l & 3) * 2;
#pragma unroll
    for (int mt = 0; mt < 4; ++mt) {
#pragma unroll
        for (int n8 = 0; n8 < 4; ++n8) {
            int d = d0 + mt * 16;
            int j = jc + n8 * 8;
            snb[(size_t)j * D_ + d]           = acc[mt][n8][0];
            snb[(size_t)(j + 1) * D_ + d]     = acc[mt][n8][1];
            snb[(size_t)j * D_ + d + 8]       = acc[mt][n8][2];
            snb[(size_t)(j + 1) * D_ + d + 8] = acc[mt][n8][3];
        }
    }
}

// ---------------- GEMM2 (mma.sync split-bf16): out = relu([emb | sn/deg] @ W^T + b)
// CTA 64(M tokens) x 128(N d_out), 4 warps n32 each; K=256 in 4 stages of 64.
// A = concat rows fp32 -> hi/lo bf16 in smem [m][k]; W from g_Whi/g_Wlo via cp.async [n][k].
// 3-term MMA: hi*Whi + hi*Wlo + lo*Whi (dropped lo*Wlo term <= 2^-16).
#define G2_ST   49152    // A_hi 8K + A_lo 8K + W_hi 16K + W_lo 16K
#define G2_SMEM (2 * G2_ST)

__device__ __forceinline__ uint32_t pkbf(__nv_bfloat16 a, __nv_bfloat16 b) {
    return ((uint32_t)__bfloat16_as_ushort(b) << 16) | __bfloat16_as_ushort(a);
}

__device__ __forceinline__ void g2_load(uint32_t sb, int s,
                                        const float* __restrict__ embb,
                                        const float* __restrict__ snb,
                                        const float* invs, int t) {
    const int st = s & 1, k0 = s * 64;
    const uint32_t ah = sb + st * G2_ST;
    const uint32_t al = ah + 8192;
    const uint32_t wh = ah + 16384;
    const uint32_t wl = ah + 32768;
    // W hi/lo: 128 n-rows x 8 x 16B each
#pragma unroll
    for (int p = 0; p < 8; ++p) {
        int cid = t + p * 128;
        int row = cid >> 3, c = cid & 7;
        uint32_t d = row * 128 + ((c * 16) ^ ((row & 7) << 4));
        CPA16(wh + d, g_Whi + (size_t)row * 256 + k0 + c * 8);
        CPA16(wl + d, g_Wlo + (size_t)row * 256 + k0 + c * 8);
    }
    // A: 64 m-rows x 16 float4 chunks; fp32 -> hi/lo bf16, 8B swizzled STS (validated r8)
#pragma unroll
    for (int p = 0; p < 8; ++p) {
        int cid = t + p * 128;
        int m = cid >> 4, c4 = cid & 15;
        float4 v;
        if (k0 < 128) {
            v = *(const float4*)(embb + (size_t)m * D_ + k0 + c4 * 4);
        } else {
            v = *(const float4*)(snb + (size_t)m * D_ + (k0 - 128) + c4 * 4);
            float iv = invs[m];
            v.x *= iv; v.y *= iv; v.z *= iv; v.w *= iv;
        }
        __nv_bfloat16 h0 = __float2bfloat16(v.x), h1 = __float2bfloat16(v.y);
        __nv_bfloat16 h2 = __float2bfloat16(v.z), h3 = __float2bfloat16(v.w);
        __nv_bfloat16 e0 = __float2bfloat16(v.x - __bfloat162float(h0));
        __nv_bfloat16 e1 = __float2bfloat16(v.y - __bfloat162float(h1));
        __nv_bfloat16 e2 = __float2bfloat16(v.z - __bfloat162float(h2));
        __nv_bfloat16 e3 = __float2bfloat16(v.w - __bfloat162float(h3));
        uint32_t hi01 = pkbf(h0, h1), hi23 = pkbf(h2, h3);
        uint32_t lo01 = pkbf(e0, e1), lo23 = pkbf(e2, e3);
        uint32_t ad = (uint32_t)m * 128 + ((((uint32_t)c4 >> 1) * 16) ^ ((m & 7) << 4)) +
                      (c4 & 1) * 8;
        asm volatile("st.shared.v2.b32 [%0], {%1,%2};" :: "r"(ah + ad), "r"(hi01), "r"(hi23) : "memory");
        asm volatile("st.shared.v2.b32 [%0], {%1,%2};" :: "r"(al + ad), "r"(lo01), "r"(lo23) : "memory");
    }
}

__global__ void __launch_bounds__(128) gemm2_mma_kernel(const float* __restrict__ emb,
                                                        const float* __restrict__ bias,
                                                        float* __restrict__ out) {
    extern __shared__ char smem[];
    __shared__ float invs[64];
    uint32_t sb = smem_to_u32(smem);
    const int t = threadIdx.x, wid = t >> 5, l = t & 31;
    const int b = blockIdx.y, r0 = blockIdx.x * 64;
    const float* embb = emb  + ((size_t)b * N_ + r0) * D_;
    const float* snb  = g_sn + ((size_t)b * N_ + r0) * D_;

    if (t < 64) invs[t] = g_invdeg[b * N_ + r0 + t];

    const int wn = wid * 32;
    const int lq = l & 15, lh = l >> 4;
    const uint32_t sx = (uint32_t)(l & 7) << 4;

    float acc[4][4][4];
#pragma unroll
    for (int mt = 0; mt < 4; ++mt)
#pragma unroll
        for (int n8 = 0; n8 < 4; ++n8)
#pragma unroll
            for (int r = 0; r < 4; ++r) acc[mt][n8][r] = 0.0f;

    g2_load(sb, 0, embb, snb, invs, t);
    CP_COMMIT();

#pragma unroll 1
    for (int s = 0; s < 4; ++s) {
        if (s + 1 < 4) {
            g2_load(sb, s + 1, embb, snb, invs, t);
            CP_COMMIT();
            CP_WAIT(1);
        } else {
            CP_WAIT(0);
        }
        __syncthreads();

        const uint32_t ah = sb + (s & 1) * G2_ST;
        const uint32_t al = ah + 8192, wh = ah + 16384, wl = ah + 32768;
#pragma unroll
        for (int ks = 0; ks < 4; ++ks) {
            uint32_t ahr[4][4], alr[4][4], whr[2][4], wlr[2][4];
            const uint32_t ko = ((uint32_t)(ks * 32 + lh * 16)) ^ sx;
#pragma unroll
            for (int mt = 0; mt < 4; ++mt) {
                uint32_t ro = (uint32_t)(mt * 16 + lq) * 128 + ko;
                LDSM4(ahr[mt], ah + ro);
                LDSM4(alr[mt], al + ro);
            }
#pragma unroll
            for (int nt = 0; nt < 2; ++nt) {
                uint32_t ro = (uint32_t)(wn + nt * 16 + lq) * 128 + ko;
                LDSM4(whr[nt], wh + ro);
                LDSM4(wlr[nt], wl + ro);
            }
#pragma unroll
            for (int mt = 0; mt < 4; ++mt)
#pragma unroll
                for (int n8 = 0; n8 < 4; ++n8) {
                    const int nt = n8 >> 1, sl = n8 & 1;
                    MMA16816(acc[mt][n8], ahr[mt], whr[nt][sl], whr[nt][sl + 2]);
                    MMA16816(acc[mt][n8], ahr[mt], wlr[nt][sl], wlr[nt][sl + 2]);
                    MMA16816(acc[mt][n8], alr[mt], whr[nt][sl], whr[nt][sl + 2]);
                }
        }
        __syncthreads();
    }

    // epilogue: bias + relu, C fragment (m=token, n=d_out)
    const int mr = l >> 2, nc = (l & 3) * 2;
    float bv[4][2];
#pragma unroll
    for (int n8 = 0; n8 < 4; ++n8) {
        bv[n8][0] = bias[wn + n8 * 8 + nc];
        bv[n8][1] = bias[wn + n8 * 8 + nc + 1];
    }
    float* outb = out + ((size_t)b * N_ + r0) * D_;
#pragma unroll
    for (int mt = 0; mt < 4; ++mt) {
#pragma unroll
        for (int n8 = 0; n8 < 4; ++n8) {
            int m = mt * 16 + mr;
            int n = wn + n8 * 8 + nc;
            float2 o0, o1;
            o0.x = fmaxf(acc[mt][n8][0] + bv[n8][0], 0.0f);
            o0.y = fmaxf(acc[mt][n8][1] + bv[n8][1], 0.0f);
            o1.x = fmaxf(acc[mt][n8][2] + bv[n8][0], 0.0f);
            o1.y = fmaxf(acc[mt][n8][3] + bv[n8][1], 0.0f);
            *(float2*)&outb[(size_t)m * D_ + n]       = o0;
            *(float2*)&outb[(size_t)(m + 8) * D_ + n] = o1;
        }
    }
}

// ---------------- launch ----------------
extern "C" void kernel_launch(void* const* d_in, const int* in_sizes, int n_in,
                              void* d_out, int out_size) {
    const float* emb  = (const float*)d_in[0];   // [8, 2048, 128]
    const float* cost = (const float*)d_in[1];   // [8, 2048, 2048]
    const float* W    = (const float*)d_in[2];   // [128, 256]
    const float* bias = (const float*)d_in[3];   // [128]
    float* out = (float*)d_out;                  // [8, 2048, 128]

    degconv_kernel<<<(B_ * N_) / 8, 256>>>(cost);
    embT_kernel<<<dim3(N_ / 32, D_ / 32, B_), 256>>>(emb);
    wsplit_kernel<<<128, 256>>>(W);

    cudaFuncSetAttribute(gemm1_mma_kernel,
                         cudaFuncAttributeMaxDynamicSharedMemorySize, G1_SMEM);
    gemm1_mma_kernel<<<dim3(N_ / 128, B_), 256, G1_SMEM>>>();

    cudaFuncSetAttribute(gemm2_mma_kernel,
                         cudaFuncAttributeMaxDynamicSharedMemorySize, G2_SMEM);
    gemm2_mma_kernel<<<dim3(N_ / 64, B_), 128, G2_SMEM>>>(emb, bias, out);
}

// round 16
// speedup vs baseline: 1.5367x; 1.0203x over previous
#include <cuda_runtime.h>
#include <cuda_bf16.h>
#include <cstdint>

#define B_ 8
#define N_ 2048
#define D_ 128

// ---------------- scratch (__device__ globals: allocation-free) ----------------
__device__ __align__(16) unsigned int g_costb16[(size_t)B_ * N_ * N_ / 2]; // bf16 [b][i][j]
__device__ __align__(16) unsigned int g_embT[(size_t)B_ * D_ * N_ / 2];    // bf16 [b][d][i]
__device__ __align__(16) float g_sn[(size_t)B_ * N_ * D_];                 // fp32 [b][j][d]
__device__ __align__(16) __nv_bfloat16 g_embhi[(size_t)B_ * N_ * D_];      // bf16 [b][i][d]
__device__ __align__(16) __nv_bfloat16 g_emblo[(size_t)B_ * N_ * D_];
__device__ __align__(16) __nv_bfloat16 g_snhi[(size_t)B_ * N_ * D_];       // bf16 [b][j][d] (inv applied)
__device__ __align__(16) __nv_bfloat16 g_snlo[(size_t)B_ * N_ * D_];
__device__ __align__(16) __nv_bfloat16 g_Whi[D_ * 2 * D_];                 // bf16 [n][k]
__device__ __align__(16) __nv_bfloat16 g_Wlo[D_ * 2 * D_];
__device__ float g_invdeg[B_ * N_];

// ---------------- helpers ----------------
__device__ __forceinline__ uint32_t smem_to_u32(const void* p) {
    uint32_t a;
    asm("{ .reg .u64 t; cvta.to.shared.u64 t, %1; cvt.u32.u64 %0, t; }" : "=r"(a) : "l"(p));
    return a;
}
#define CPA16(dst, src) \
    asm volatile("cp.async.cg.shared.global [%0], [%1], 16;" :: "r"(dst), "l"(src) : "memory")
#define CP_COMMIT() asm volatile("cp.async.commit_group;" ::: "memory")
#define CP_WAIT(n)  asm volatile("cp.async.wait_group %0;" :: "n"(n) : "memory")

#define LDSM4(r, addr) \
    asm volatile("ldmatrix.sync.aligned.m8n8.x4.shared.b16 {%0,%1,%2,%3}, [%4];" \
                 : "=r"((r)[0]), "=r"((r)[1]), "=r"((r)[2]), "=r"((r)[3]) : "r"(addr))
#define LDSM4T(r, addr) \
    asm volatile("ldmatrix.sync.aligned.m8n8.x4.trans.shared.b16 {%0,%1,%2,%3}, [%4];" \
                 : "=r"((r)[0]), "=r"((r)[1]), "=r"((r)[2]), "=r"((r)[3]) : "r"(addr))
#define MMA16816(c, a, b0, b1) \
    asm volatile("mma.sync.aligned.m16n8k16.row.col.f32.bf16.bf16.f32 " \
                 "{%0,%1,%2,%3}, {%4,%5,%6,%7}, {%8,%9}, {%0,%1,%2,%3};" \
                 : "+f"((c)[0]), "+f"((c)[1]), "+f"((c)[2]), "+f"((c)[3]) \
                 : "r"((a)[0]), "r"((a)[1]), "r"((a)[2]), "r"((a)[3]), "r"(b0), "r"(b1))

__device__ __forceinline__ uint32_t pkbf(__nv_bfloat16 a, __nv_bfloat16 b) {
    return ((uint32_t)__bfloat16_as_ushort(b) << 16) | __bfloat16_as_ushort(a);
}

// ---------------- degree + fp32->bf16 cost conversion (fused single pass) ----------------
__global__ void __launch_bounds__(256) degconv_kernel(const float* __restrict__ cost) {
    int row  = blockIdx.x * 8 + (threadIdx.x >> 5);
    int lane = threadIdx.x & 31;
    const float4* r4 = (const float4*)(cost + (size_t)row * N_);
    unsigned int* w = g_costb16 + (size_t)row * (N_ / 2);
    int cnt = 0;
#pragma unroll
    for (int it = 0; it < 16; ++it) {
        float4 v = r4[it * 32 + lane];
        cnt += (v.x != 0.0f) + (v.y != 0.0f) + (v.z != 0.0f) + (v.w != 0.0f);
        unsigned int p0, p1;
        asm("cvt.rn.satfinite.bf16x2.f32 %0, %1, %2;" : "=r"(p0) : "f"(v.y), "f"(v.x));
        asm("cvt.rn.satfinite.bf16x2.f32 %0, %1, %2;" : "=r"(p1) : "f"(v.w), "f"(v.z));
        *(uint2*)&w[it * 64 + lane * 2] = make_uint2(p0, p1);
    }
#pragma unroll
    for (int off = 16; off > 0; off >>= 1)
        cnt += __shfl_down_sync(0xffffffffu, cnt, off);
    if (lane == 0) g_invdeg[row] = 1.0f / (float)cnt;
}

// ---------------- embT + emb hi/lo split: reads emb once ----------------
__global__ void __launch_bounds__(256) embT_kernel(const float* __restrict__ emb) {
    __shared__ float tile[32][33];
    int b = blockIdx.z, i0 = blockIdx.x * 32, d0 = blockIdx.y * 32;
    int tx = threadIdx.x & 31, ty = threadIdx.x >> 5;
    const float* src = emb + ((size_t)b * N_ + i0) * D_ + d0;
#pragma unroll
    for (int k = 0; k < 4; ++k) {
        float v = src[(ty + 8 * k) * D_ + tx];
        tile[ty + 8 * k][tx] = v;
        __nv_bfloat16 h = __float2bfloat16(v);
        size_t idx = ((size_t)b * N_ + i0 + ty + 8 * k) * D_ + d0 + tx;
        g_embhi[idx] = h;
        g_emblo[idx] = __float2bfloat16(v - __bfloat162float(h));
    }
    __syncthreads();
    __nv_bfloat16* dst = (__nv_bfloat16*)g_embT + ((size_t)b * D_ + d0) * N_ + i0;
#pragma unroll
    for (int k = 0; k < 4; ++k)
        dst[(ty + 8 * k) * N_ + tx] = __float2bfloat16(tile[tx][ty + 8 * k]);
}

// ---------------- W split: Whi = bf16(W), Wlo = bf16(W - Whi) ----------------
__global__ void wsplit_kernel(const float* __restrict__ W) {
    int i = blockIdx.x * 256 + threadIdx.x;   // 128 blocks x 256 = 32768
    float w = W[i];
    __nv_bfloat16 h = __float2bfloat16(w);
    g_Whi[i] = h;
    g_Wlo[i] = __float2bfloat16(w - __bfloat162float(h));
}

// ---------------- sn split (inv applied): snhi/lo = split(sn * invdeg[j]) ----------------
__global__ void __launch_bounds__(256) snsplit_kernel() {
    size_t i4 = ((size_t)blockIdx.x * 256 + threadIdx.x) * 4;   // grid 2048
    float4 v = *(const float4*)(g_sn + i4);
    float inv = g_invdeg[i4 >> 7];
    v.x *= inv; v.y *= inv; v.z *= inv; v.w *= inv;
    __nv_bfloat16 h0 = __float2bfloat16(v.x), h1 = __float2bfloat16(v.y);
    __nv_bfloat16 h2 = __float2bfloat16(v.z), h3 = __float2bfloat16(v.w);
    *(uint2*)&g_snhi[i4] = make_uint2(pkbf(h0, h1), pkbf(h2, h3));
    __nv_bfloat16 l0 = __float2bfloat16(v.x - __bfloat162float(h0));
    __nv_bfloat16 l1 = __float2bfloat16(v.y - __bfloat162float(h1));
    __nv_bfloat16 l2 = __float2bfloat16(v.z - __bfloat162float(h2));
    __nv_bfloat16 l3 = __float2bfloat16(v.w - __bfloat162float(h3));
    *(uint2*)&g_snlo[i4] = make_uint2(pkbf(l0, l1), pkbf(l2, l3));
}

// ---------------- GEMM1 (mma.sync bf16): sn[b][j][d] = sum_i cost[b,i,j]*emb[b,i,d]
// CTA 128(d=M) x 64(j=N) -> grid 256, 2 CTAs/SM. 8 warps 64x16 (2Mx4N).
// A [128][64] bf16 rows 128B; B [64][64] bf16 rows 128B (round-8-validated layout).
#define G1_STAGE 24576   // A 16KB + B 8KB
#define G1_SMEM  (2 * G1_STAGE)

__device__ __forceinline__ void g1_load(uint32_t sb, int st,
                                        const __nv_bfloat16* __restrict__ costb,
                                        const __nv_bfloat16* __restrict__ embTb,
                                        int i0, int j0, int t) {
    uint32_t abase = sb + st * G1_STAGE;
    uint32_t bbase = abase + 16384;
#pragma unroll
    for (int p = 0; p < 4; ++p) {           // A: 128 rows x 8 x 16B = 1024 chunks
        int ca = t + p * 256;
        int row = ca >> 3, c = ca & 7;
        uint32_t dst = abase + row * 128 + ((c * 16) ^ ((row & 7) << 4));
        CPA16(dst, embTb + (size_t)row * N_ + i0 + c * 8);
    }
#pragma unroll
    for (int p = 0; p < 2; ++p) {           // B: 64 rows x 8 x 16B = 512 chunks
        int cb = t + p * 256;
        int row = cb >> 3, jc = cb & 7;
        uint32_t dst = bbase + row * 128 + ((jc * 16) ^ ((row & 7) << 4));
        CPA16(dst, costb + (size_t)(i0 + row) * N_ + j0 + jc * 8);
    }
}

__global__ void __launch_bounds__(256) gemm1_mma_kernel() {
    extern __shared__ char smem[];
    uint32_t sb = smem_to_u32(smem);
    const int t = threadIdx.x, wid = t >> 5, l = t & 31;
    const int b = blockIdx.y, j0 = blockIdx.x * 64;
    const __nv_bfloat16* costb = (const __nv_bfloat16*)g_costb16 + (size_t)b * N_ * N_;
    const __nv_bfloat16* embTb = (const __nv_bfloat16*)g_embT + (size_t)b * D_ * N_;

    const int wm = (wid & 1) * 64;          // d offset (M: 2 warps)
    const int wn = (wid >> 1) * 16;         // j offset (N: 4 warps x 16)
    const int lq = l & 15, lh = l >> 4;
    const uint32_t sx = (uint32_t)(l & 7) << 4;

    float acc[4][2][4];
#pragma unroll
    for (int mt = 0; mt < 4; ++mt)
#pragma unroll
        for (int n8 = 0; n8 < 2; ++n8)
#pragma unroll
            for (int r = 0; r < 4; ++r) acc[mt][n8][r] = 0.0f;

    g1_load(sb, 0, costb, embTb, 0, j0, t);
    CP_COMMIT();

#pragma unroll 1
    for (int c = 0; c < 32; ++c) {
        if (c + 1 < 32) {
            g1_load(sb, (c + 1) & 1, costb, embTb, (c + 1) * 64, j0, t);
            CP_COMMIT();
            CP_WAIT(1);
        } else {
            CP_WAIT(0);
        }
        __syncthreads();

        uint32_t abase = sb + (c & 1) * G1_STAGE;
        uint32_t bbase = abase + 16384;
#pragma unroll
        for (int ks = 0; ks < 4; ++ks) {
            uint32_t a[4][4], bf[4];
#pragma unroll
            for (int mt = 0; mt < 4; ++mt) {
                uint32_t addr = abase + (uint32_t)(wm + mt * 16 + lq) * 128 +
                                (((uint32_t)(ks * 32 + lh * 16)) ^ sx);
                LDSM4(a[mt], addr);
            }
            {
                uint32_t addr = bbase + (uint32_t)(ks * 16 + lq) * 128 +
                                (((uint32_t)((wn + lh * 8) * 2)) ^ sx);
                LDSM4T(bf, addr);
            }
#pragma unroll
            for (int mt = 0; mt < 4; ++mt) {
                MMA16816(acc[mt][0], a[mt], bf[0], bf[1]);
                MMA16816(acc[mt][1], a[mt], bf[2], bf[3]);
            }
        }
        __syncthreads();
    }

    // epilogue: acc (m=d, n=j) -> g_sn[b][j][d]
    float* snb = g_sn + (size_t)b * N_ * D_;
    const int d0 = wm + (l >> 2);
    const int jc = j0 + wn + (l & 3) * 2;
#pragma unroll
    for (int mt = 0; mt < 4; ++mt) {
#pragma unroll
        for (int n8 = 0; n8 < 2; ++n8) {
            int d = d0 + mt * 16;
            int j = jc + n8 * 8;
            snb[(size_t)j * D_ + d]           = acc[mt][n8][0];
            snb[(size_t)(j + 1) * D_ + d]     = acc[mt][n8][1];
            snb[(size_t)j * D_ + d + 8]       = acc[mt][n8][2];
            snb[(size_t)(j + 1) * D_ + d + 8] = acc[mt][n8][3];
        }
    }
}

// ---------------- GEMM2 (mma.sync split-bf16, precomputed splits):
// out = relu([emb | sn/deg] @ W^T + b); CTA 64(M) x 128(N), 4 warps n32;
// K=256 in 4 stages; A from g_emb{hi,lo}/g_sn{hi,lo} via pure cp.async.
#define G2_ST   49152    // A_hi 8K + A_lo 8K + W_hi 16K + W_lo 16K
#define G2_SMEM (2 * G2_ST)

__device__ __forceinline__ void g2_load(uint32_t sb, int s,
                                        const __nv_bfloat16* __restrict__ ehib,
                                        const __nv_bfloat16* __restrict__ elob,
                                        const __nv_bfloat16* __restrict__ shib,
                                        const __nv_bfloat16* __restrict__ slob,
                                        int t) {
    const int st = s & 1, k0 = s * 64;
    const uint32_t ah = sb + st * G2_ST;
    const uint32_t al = ah + 8192;
    const uint32_t wh = ah + 16384;
    const uint32_t wl = ah + 32768;
    // W hi/lo: 128 n-rows x 8 x 16B each
#pragma unroll
    for (int p = 0; p < 8; ++p) {
        int cid = t + p * 128;
        int row = cid >> 3, c = cid & 7;
        uint32_t d = row * 128 + ((c * 16) ^ ((row & 7) << 4));
        CPA16(wh + d, g_Whi + (size_t)row * 256 + k0 + c * 8);
        CPA16(wl + d, g_Wlo + (size_t)row * 256 + k0 + c * 8);
    }
    // A hi/lo: 64 m-rows x 8 x 16B each (64 bf16 per row)
    const __nv_bfloat16* hsrc = (k0 < 128) ? (ehib + k0) : (shib + (k0 - 128));
    const __nv_bfloat16* lsrc = (k0 < 128) ? (elob + k0) : (slob + (k0 - 128));
#pragma unroll
    for (int p = 0; p < 4; ++p) {
        int cid = t + p * 128;
        int row = cid >> 3, c = cid & 7;
        uint32_t d = row * 128 + ((c * 16) ^ ((row & 7) << 4));
        CPA16(ah + d, hsrc + (size_t)row * D_ + c * 8);
        CPA16(al + d, lsrc + (size_t)row * D_ + c * 8);
    }
}

__global__ void __launch_bounds__(128) gemm2_mma_kernel(const float* __restrict__ bias,
                                                        float* __restrict__ out) {
    extern __shared__ char smem[];
    uint32_t sb = smem_to_u32(smem);
    const int t = threadIdx.x, wid = t >> 5, l = t & 31;
    const int b = blockIdx.y, r0 = blockIdx.x * 64;
    const __nv_bfloat16* ehib = g_embhi + ((size_t)b * N_ + r0) * D_;
    const __nv_bfloat16* elob = g_emblo + ((size_t)b * N_ + r0) * D_;
    const __nv_bfloat16* shib = g_snhi + ((size_t)b * N_ + r0) * D_;
    const __nv_bfloat16* slob = g_snlo + ((size_t)b * N_ + r0) * D_;

    const int wn = wid * 32;
    const int lq = l & 15, lh = l >> 4;
    const uint32_t sx = (uint32_t)(l & 7) << 4;

    float acc[4][4][4];
#pragma unroll
    for (int mt = 0; mt < 4; ++mt)
#pragma unroll
        for (int n8 = 0; n8 < 4; ++n8)
#pragma unroll
            for (int r = 0; r < 4; ++r) acc[mt][n8][r] = 0.0f;

    g2_load(sb, 0, ehib, elob, shib, slob, t);
    CP_COMMIT();

#pragma unroll 1
    for (int s = 0; s < 4; ++s) {
        if (s + 1 < 4) {
            g2_load(sb, s + 1, ehib, elob, shib, slob, t);
            CP_COMMIT();
            CP_WAIT(1);
        } else {
            CP_WAIT(0);
        }
        __syncthreads();

        const uint32_t ah = sb + (s & 1) * G2_ST;
        const uint32_t al = ah + 8192, wh = ah + 16384, wl = ah + 32768;
#pragma unroll
        for (int ks = 0; ks < 4; ++ks) {
            uint32_t ahr[4][4], alr[4][4], whr[2][4], wlr[2][4];
            const uint32_t ko = ((uint32_t)(ks * 32 + lh * 16)) ^ sx;
#pragma unroll
            for (int mt = 0; mt < 4; ++mt) {
                uint32_t ro = (uint32_t)(mt * 16 + lq) * 128 + ko;
                LDSM4(ahr[mt], ah + ro);
                LDSM4(alr[mt], al + ro);
            }
#pragma unroll
            for (int nt = 0; nt < 2; ++nt) {
                uint32_t ro = (uint32_t)(wn + nt * 16 + lq) * 128 + ko;
                LDSM4(whr[nt], wh + ro);
                LDSM4(wlr[nt], wl + ro);
            }
#pragma unroll
            for (int mt = 0; mt < 4; ++mt)
#pragma unroll
                for (int n8 = 0; n8 < 4; ++n8) {
                    const int nt = n8 >> 1, sl = n8 & 1;
                    MMA16816(acc[mt][n8], ahr[mt], whr[nt][sl], whr[nt][sl + 2]);
                    MMA16816(acc[mt][n8], ahr[mt], wlr[nt][sl], wlr[nt][sl + 2]);
                    MMA16816(acc[mt][n8], alr[mt], whr[nt][sl], whr[nt][sl + 2]);
                }
        }
        __syncthreads();
    }

    // epilogue: bias + relu, C fragment (m=token, n=d_out)
    const int mr = l >> 2, nc = (l & 3) * 2;
    float bv[4][2];
#pragma unroll
    for (int n8 = 0; n8 < 4; ++n8) {
        bv[n8][0] = bias[wn + n8 * 8 + nc];
        bv[n8][1] = bias[wn + n8 * 8 + nc + 1];
    }
    float* outb = out + ((size_t)b * N_ + r0) * D_;
#pragma unroll
    for (int mt = 0; mt < 4; ++mt) {
#pragma unroll
        for (int n8 = 0; n8 < 4; ++n8) {
            int m = mt * 16 + mr;
            int n = wn + n8 * 8 + nc;
            float2 o0, o1;
            o0.x = fmaxf(acc[mt][n8][0] + bv[n8][0], 0.0f);
            o0.y = fmaxf(acc[mt][n8][1] + bv[n8][1], 0.0f);
            o1.x = fmaxf(acc[mt][n8][2] + bv[n8][0], 0.0f);
            o1.y = fmaxf(acc[mt][n8][3] + bv[n8][1], 0.0f);
            *(float2*)&outb[(size_t)m * D_ + n]       = o0;
            *(float2*)&outb[(size_t)(m + 8) * D_ + n] = o1;
        }
    }
}

// ---------------- launch ----------------
extern "C" void kernel_launch(void* const* d_in, const int* in_sizes, int n_in,
                              void* d_out, int out_size) {
    const float* emb  = (const float*)d_in[0];   // [8, 2048, 128]
    const float* cost = (const float*)d_in[1];   // [8, 2048, 2048]
    const float* W    = (const float*)d_in[2];   // [128, 256]
    const float* bias = (const float*)d_in[3];   // [128]
    float* out = (float*)d_out;                  // [8, 2048, 128]

    degconv_kernel<<<(B_ * N_) / 8, 256>>>(cost);
    embT_kernel<<<dim3(N_ / 32, D_ / 32, B_), 256>>>(emb);
    wsplit_kernel<<<128, 256>>>(W);

    cudaFuncSetAttribute(gemm1_mma_kernel,
                         cudaFuncAttributeMaxDynamicSharedMemorySize, G1_SMEM);
    gemm1_mma_kernel<<<dim3(N_ / 64, B_), 256, G1_SMEM>>>();

    snsplit_kernel<<<(B_ * N_ * D_) / 1024, 256>>>();

    cudaFuncSetAttribute(gemm2_mma_kernel,
                         cudaFuncAttributeMaxDynamicSharedMemorySize, G2_SMEM);
    gemm2_mma_kernel<<<dim3(N_ / 64, B_), 128, G2_SMEM>>>(bias, out);
}